// round 1
// baseline (speedup 1.0000x reference)
#include <cuda_runtime.h>

#define KE_CONST 14.399645351950548f
#define MAX_NODES 131072

// Scratch (no cudaMalloc allowed): per-node (z, z^p * d) table + derived params.
__device__ float2 g_node[MAX_NODES];
__device__ float  g_par[8];   // [0..3] = -a_k (natural-log exponent coeffs), [4..7] = normalized c_k

__device__ __forceinline__ float softplus_f(float x) {
    // stable softplus: max(x,0) + log1p(exp(-|x|))
    return fmaxf(x, 0.0f) + log1pf(__expf(-fabsf(x)));
}

__global__ void setup_params_kernel(const float* __restrict__ a1, const float* __restrict__ a2,
                                    const float* __restrict__ a3, const float* __restrict__ a4,
                                    const float* __restrict__ c1, const float* __restrict__ c2,
                                    const float* __restrict__ c3, const float* __restrict__ c4) {
    if (threadIdx.x == 0 && blockIdx.x == 0) {
        float A1 = softplus_f(a1[0]), A2 = softplus_f(a2[0]);
        float A3 = softplus_f(a3[0]), A4 = softplus_f(a4[0]);
        float C1 = softplus_f(c1[0]), C2 = softplus_f(c2[0]);
        float C3 = softplus_f(c3[0]), C4 = softplus_f(c4[0]);
        float s = 1.0f / (C1 + C2 + C3 + C4);
        g_par[0] = -A1; g_par[1] = -A2; g_par[2] = -A3; g_par[3] = -A4;
        g_par[4] = C1 * s; g_par[5] = C2 * s; g_par[6] = C3 * s; g_par[7] = C4 * s;
    }
}

// Per-node precompute: (z, z^p * d). Hoists 2 powf per edge (12.8M) down to 100K.
__global__ void node_kernel(const float* __restrict__ z,
                            const float* __restrict__ p_raw,
                            const float* __restrict__ d_raw, int n) {
    int i = blockIdx.x * blockDim.x + threadIdx.x;
    if (i >= n) return;
    float p = softplus_f(p_raw[0]);
    float d = softplus_f(d_raw[0]);
    float zi = z[i];
    g_node[i] = make_float2(zi, __powf(zi, p) * d);
}

__global__ void __launch_bounds__(256)
edge_kernel(const float* __restrict__ cut, const float* __restrict__ len,
            const int* __restrict__ snd, const int* __restrict__ rcv,
            float* __restrict__ out, int E) {
    int i4 = blockIdx.x * blockDim.x + threadIdx.x;
    long long base = (long long)i4 * 4;
    if (base >= E) return;

    // params broadcast via L1/L2 (uniform across warp)
    const float b1 = g_par[0], b2 = g_par[1], b3 = g_par[2], b4 = g_par[3];
    const float c1 = g_par[4], c2 = g_par[5], c3 = g_par[6], c4 = g_par[7];

    float4 Lv, Cv; int4 Sv, Rv;
    if (base + 3 < E) {
        Lv = *reinterpret_cast<const float4*>(len + base);
        Cv = *reinterpret_cast<const float4*>(cut + base);
        Sv = *reinterpret_cast<const int4*>(snd + base);
        Rv = *reinterpret_cast<const int4*>(rcv + base);
    } else {
        float* lp = &Lv.x; float* cp = &Cv.x; int* sp = &Sv.x; int* rp = &Rv.x;
        for (int k = 0; k < 4; k++) {
            long long e = base + k;
            lp[k] = (e < E) ? len[e] : 2.0f;   // L >= 1.5 -> w == 0 -> no-op
            cp[k] = (e < E) ? cut[e] : 0.0f;
            sp[k] = (e < E) ? snd[e] : 0;
            rp[k] = (e < E) ? rcv[e] : 0;
        }
    }

    const float* lp = &Lv.x; const float* cp = &Cv.x;
    const int* sp = &Sv.x; const int* rp = &Rv.x;

#pragma unroll
    for (int k = 0; k < 4; k++) {
        float L = lp[k];
        float cc = L * (1.0f / 1.5f);          // switch argument, x_on=0, x_off=1.5
        if (cc >= 1.0f) continue;              // w == 0 exactly: ~60% of edges skipped
        // _sigma(1-cc) and _sigma(cc); cc >= 1/3 here so no clamp needed on cc
        float s1 = __expf(-__fdividef(1.0f, fmaxf(1.0f - cc, 1e-12f)));
        float s0 = __expf(-__fdividef(1.0f, cc));
        float w  = __fdividef(s1, s1 + s0 + 1e-12f);

        int s = sp[k], r = rp[k];
        float2 nj = g_node[s];                 // (z_j, z_j^p * d)
        float2 ni = g_node[r];                 // (z_i, z_i^p * d)

        float x = KE_CONST * cp[k] * ni.x * nj.x * __fdividef(1.0f, fmaxf(L, 1e-6f));
        float t = L * (ni.y + nj.y);           // rzd
        float y = c1 * __expf(b1 * t) + c2 * __expf(b2 * t)
                + c3 * __expf(b3 * t) + c4 * __expf(b4 * t);

        atomicAdd(out + r, 0.5f * w * x * y);
    }
}

extern "C" void kernel_launch(void* const* d_in, const int* in_sizes, int n_in,
                              void* d_out, int out_size) {
    // Inputs (metadata order): atomic_numbers, cutoffs, senders, receivers,
    // lengths, [num_nodes?], a1_raw..a4_raw, c1_raw..c4_raw, p_raw, d_raw.
    // Params are robustly indexed from the END so the scalar num_nodes slot
    // (present or not) doesn't matter.
    const float* z   = (const float*)d_in[0];
    const float* cut = (const float*)d_in[1];
    const int*   snd = (const int*)  d_in[2];
    const int*   rcv = (const int*)  d_in[3];
    const float* len = (const float*)d_in[4];

    int pb = n_in - 10;
    const float* a1 = (const float*)d_in[pb + 0];
    const float* a2 = (const float*)d_in[pb + 1];
    const float* a3 = (const float*)d_in[pb + 2];
    const float* a4 = (const float*)d_in[pb + 3];
    const float* c1 = (const float*)d_in[pb + 4];
    const float* c2 = (const float*)d_in[pb + 5];
    const float* c3 = (const float*)d_in[pb + 6];
    const float* c4 = (const float*)d_in[pb + 7];
    const float* pr = (const float*)d_in[pb + 8];
    const float* dr = (const float*)d_in[pb + 9];

    int N = in_sizes[0];
    int E = in_sizes[2];
    if (N > MAX_NODES) N = MAX_NODES;

    float* out = (float*)d_out;

    // Output is poisoned (0xAA) before timing: zero it (segment_sum baseline).
    cudaMemsetAsync(d_out, 0, (size_t)out_size * sizeof(float), 0);

    setup_params_kernel<<<1, 32>>>(a1, a2, a3, a4, c1, c2, c3, c4);
    node_kernel<<<(N + 255) / 256, 256>>>(z, pr, dr, N);

    int n4 = (E + 3) / 4;
    edge_kernel<<<(n4 + 255) / 256, 256>>>(cut, len, snd, rcv, out, E);
}

// round 2
// speedup vs baseline: 1.0528x; 1.0528x over previous
#include <cuda_runtime.h>

#define KE_CONST 14.399645351950548f
#define MAX_NODES 131072

// Scratch (no cudaMalloc allowed): per-node (z, z^p * d) table + derived params.
__device__ float2 g_node[MAX_NODES];
__device__ float  g_par[8];   // [0..3] = -a_k, [4..7] = normalized c_k

__device__ __forceinline__ float softplus_f(float x) {
    // stable softplus: max(x,0) + log1p(exp(-|x|))
    return fmaxf(x, 0.0f) + log1pf(__expf(-fabsf(x)));
}

// Fused: zero output + per-node (z, z^p*d) precompute + (thread 0) param derivation.
__global__ void node_kernel(const float* __restrict__ z,
                            const float* __restrict__ p_raw,
                            const float* __restrict__ d_raw,
                            const float* __restrict__ a1, const float* __restrict__ a2,
                            const float* __restrict__ a3, const float* __restrict__ a4,
                            const float* __restrict__ c1, const float* __restrict__ c2,
                            const float* __restrict__ c3, const float* __restrict__ c4,
                            float* __restrict__ out, int n, int n_out) {
    int i = blockIdx.x * blockDim.x + threadIdx.x;
    if (i == 0) {
        float A1 = softplus_f(a1[0]), A2 = softplus_f(a2[0]);
        float A3 = softplus_f(a3[0]), A4 = softplus_f(a4[0]);
        float C1 = softplus_f(c1[0]), C2 = softplus_f(c2[0]);
        float C3 = softplus_f(c3[0]), C4 = softplus_f(c4[0]);
        float s = 1.0f / (C1 + C2 + C3 + C4);
        g_par[0] = -A1; g_par[1] = -A2; g_par[2] = -A3; g_par[3] = -A4;
        g_par[4] = C1 * s; g_par[5] = C2 * s; g_par[6] = C3 * s; g_par[7] = C4 * s;
    }
    if (i < n_out) out[i] = 0.0f;
    if (i < n) {
        float p = softplus_f(p_raw[0]);
        float d = softplus_f(d_raw[0]);
        float zi = z[i];
        g_node[i] = make_float2(zi, __powf(zi, p) * d);
    }
}

__global__ void __launch_bounds__(256)
edge_kernel(const float* __restrict__ cut, const float* __restrict__ len,
            const int* __restrict__ snd, const int* __restrict__ rcv,
            float* __restrict__ out, int E) {
    int i4 = blockIdx.x * blockDim.x + threadIdx.x;
    long long base = (long long)i4 * 4;
    if (base >= E) return;

    const float b1 = g_par[0], b2 = g_par[1], b3 = g_par[2], b4 = g_par[3];
    const float c1 = g_par[4], c2 = g_par[5], c3 = g_par[6], c4 = g_par[7];

    float4 Lv, Cv; int4 Sv, Rv;
    if (base + 3 < E) {
        Lv = *reinterpret_cast<const float4*>(len + base);
        Cv = *reinterpret_cast<const float4*>(cut + base);
        Sv = *reinterpret_cast<const int4*>(snd + base);
        Rv = *reinterpret_cast<const int4*>(rcv + base);
    } else {
        float* lp = &Lv.x; float* cp = &Cv.x; int* sp = &Sv.x; int* rp = &Rv.x;
        for (int k = 0; k < 4; k++) {
            long long e = base + k;
            lp[k] = (e < E) ? len[e] : 2.0f;   // L >= 1.5 -> w == 0 -> no-op
            cp[k] = (e < E) ? cut[e] : 0.0f;
            sp[k] = (e < E) ? snd[e] : 0;
            rp[k] = (e < E) ? rcv[e] : 0;
        }
    }

    const float* lp = &Lv.x; const float* cp = &Cv.x;
    const int* sp = &Sv.x; const int* rp = &Rv.x;

#pragma unroll
    for (int k = 0; k < 4; k++) {
        float L = lp[k];
        float cc = L * (1.0f / 1.5f);          // switch argument, x_on=0, x_off=1.5
        if (cc >= 1.0f) continue;              // w == 0 exactly: ~60% of edges skipped

        // w = s1/(s1+s0+eps) = 1/(1 + exp(1/(1-cc) - 1/cc))   (single exp)
        float f = __fdividef(1.0f, 1.0f - cc) - __fdividef(1.0f, cc);
        float w = __fdividef(1.0f, 1.0f + __expf(f));

        int s = sp[k], r = rp[k];
        float2 nj = g_node[s];                 // (z_j, z_j^p * d)
        float2 ni = g_node[r];                 // (z_i, z_i^p * d)

        float x = KE_CONST * cp[k] * ni.x * nj.x * __fdividef(1.0f, fmaxf(L, 1e-6f));
        float t = L * (ni.y + nj.y);           // rzd
        float y = c1 * __expf(b1 * t) + c2 * __expf(b2 * t)
                + c3 * __expf(b3 * t) + c4 * __expf(b4 * t);

        atomicAdd(out + r, 0.5f * w * x * y);
    }
}

extern "C" void kernel_launch(void* const* d_in, const int* in_sizes, int n_in,
                              void* d_out, int out_size) {
    const float* z   = (const float*)d_in[0];
    const float* cut = (const float*)d_in[1];
    const int*   snd = (const int*)  d_in[2];
    const int*   rcv = (const int*)  d_in[3];
    const float* len = (const float*)d_in[4];

    // Param pointers indexed from the END (num_nodes slot may or may not be a buffer).
    int pb = n_in - 10;
    const float* a1 = (const float*)d_in[pb + 0];
    const float* a2 = (const float*)d_in[pb + 1];
    const float* a3 = (const float*)d_in[pb + 2];
    const float* a4 = (const float*)d_in[pb + 3];
    const float* c1 = (const float*)d_in[pb + 4];
    const float* c2 = (const float*)d_in[pb + 5];
    const float* c3 = (const float*)d_in[pb + 6];
    const float* c4 = (const float*)d_in[pb + 7];
    const float* pr = (const float*)d_in[pb + 8];
    const float* dr = (const float*)d_in[pb + 9];

    int N = in_sizes[0];
    int E = in_sizes[2];
    if (N > MAX_NODES) N = MAX_NODES;

    float* out = (float*)d_out;

    int cover = (N > out_size) ? N : out_size;
    node_kernel<<<(cover + 255) / 256, 256>>>(z, pr, dr, a1, a2, a3, a4,
                                              c1, c2, c3, c4, out, N, out_size);

    int n4 = (E + 3) / 4;
    edge_kernel<<<(n4 + 255) / 256, 256>>>(cut, len, snd, rcv, out, E);
}